// round 5
// baseline (speedup 1.0000x reference)
#include <cuda_runtime.h>
#include <cuda_bf16.h>
#include <math.h>
#include <stdint.h>

// Problem constants
#define NB 32            // batch
#define TT 1024          // timesteps
#define DD 512           // input dim
#define HH 512           // hidden dim
#define G4 2048          // 4*H
#define MROWS (NB * TT)  // 32768

// Recurrent kernel config
#define RBLOCKS 128      // persistent blocks, 1 per SM
#define RTHREADS 256
#define JPB 4            // h-columns per block
#define CPB 16           // gate columns per block

// Scratch (device globals; no cudaMalloc allowed)
__device__ float g_xw[(size_t)MROWS * G4];   // 268 MB: x @ Wx + b
__device__ unsigned g_bar[2];                // [0]=arrival count, [1]=sense; zeroed per launch

// h exchanged in MMA A-fragment layout: [buf][mt][ktile][lane] -> uint4 (a0..a3)
__device__ uint4 g_hfragHI[2][2][32][32];
__device__ uint4 g_hfragLO[2][2][32][32];

// bf16 hi/lo split buffers for tensor-core phase 1
__device__ __nv_bfloat16 g_xhi[(size_t)MROWS * DD];
__device__ __nv_bfloat16 g_xlo[(size_t)MROWS * DD];
__device__ __nv_bfloat16 g_whi[(size_t)DD * G4];
__device__ __nv_bfloat16 g_wlo[(size_t)DD * G4];

// ---------------------------------------------------------------------------
// fp32 -> bf16 hi + lo split
// ---------------------------------------------------------------------------
__device__ __forceinline__ void split1(float v, __nv_bfloat16& h, __nv_bfloat16& l)
{
    h = __float2bfloat16(v);
    l = __float2bfloat16(v - __bfloat162float(h));
}

__global__ void __launch_bounds__(256) split_kernel_x(const float* __restrict__ src)
{
    size_t i = (size_t)blockIdx.x * blockDim.x + threadIdx.x;
    size_t n4 = (size_t)MROWS * DD / 4;
    if (i >= n4) return;
    float4 v = ((const float4*)src)[i];
    __nv_bfloat16 h0, h1, h2, h3, l0, l1, l2, l3;
    split1(v.x, h0, l0); split1(v.y, h1, l1);
    split1(v.z, h2, l2); split1(v.w, h3, l3);
    ((__nv_bfloat162*)g_xhi)[2 * i]     = __nv_bfloat162(h0, h1);
    ((__nv_bfloat162*)g_xhi)[2 * i + 1] = __nv_bfloat162(h2, h3);
    ((__nv_bfloat162*)g_xlo)[2 * i]     = __nv_bfloat162(l0, l1);
    ((__nv_bfloat162*)g_xlo)[2 * i + 1] = __nv_bfloat162(l2, l3);
}

__global__ void __launch_bounds__(256) split_kernel_w(const float* __restrict__ src)
{
    size_t i = (size_t)blockIdx.x * blockDim.x + threadIdx.x;
    size_t n4 = (size_t)DD * G4 / 4;
    if (i >= n4) return;
    float4 v = ((const float4*)src)[i];
    __nv_bfloat16 h0, h1, h2, h3, l0, l1, l2, l3;
    split1(v.x, h0, l0); split1(v.y, h1, l1);
    split1(v.z, h2, l2); split1(v.w, h3, l3);
    ((__nv_bfloat162*)g_whi)[2 * i]     = __nv_bfloat162(h0, h1);
    ((__nv_bfloat162*)g_whi)[2 * i + 1] = __nv_bfloat162(h2, h3);
    ((__nv_bfloat162*)g_wlo)[2 * i]     = __nv_bfloat162(l0, l1);
    ((__nv_bfloat162*)g_wlo)[2 * i + 1] = __nv_bfloat162(l2, l3);
}

// ---------------------------------------------------------------------------
// PTX wrappers
// ---------------------------------------------------------------------------
__device__ __forceinline__ void ldsm_x4(uint32_t& r0, uint32_t& r1, uint32_t& r2,
                                        uint32_t& r3, const void* p)
{
    uint32_t a = (uint32_t)__cvta_generic_to_shared(p);
    asm volatile("ldmatrix.sync.aligned.m8n8.x4.shared.b16 {%0,%1,%2,%3}, [%4];"
                 : "=r"(r0), "=r"(r1), "=r"(r2), "=r"(r3) : "r"(a));
}

__device__ __forceinline__ void ldsm_x4_t(uint32_t& r0, uint32_t& r1, uint32_t& r2,
                                          uint32_t& r3, const void* p)
{
    uint32_t a = (uint32_t)__cvta_generic_to_shared(p);
    asm volatile("ldmatrix.sync.aligned.m8n8.x4.trans.shared.b16 {%0,%1,%2,%3}, [%4];"
                 : "=r"(r0), "=r"(r1), "=r"(r2), "=r"(r3) : "r"(a));
}

__device__ __forceinline__ void mma_bf16(float* c, const uint32_t* a,
                                         uint32_t b0, uint32_t b1)
{
    asm volatile(
        "mma.sync.aligned.m16n8k16.row.col.f32.bf16.bf16.f32 "
        "{%0,%1,%2,%3},{%4,%5,%6,%7},{%8,%9},{%0,%1,%2,%3};"
        : "+f"(c[0]), "+f"(c[1]), "+f"(c[2]), "+f"(c[3])
        : "r"(a[0]), "r"(a[1]), "r"(a[2]), "r"(a[3]), "r"(b0), "r"(b1));
}

// ---------------------------------------------------------------------------
// Phase 1 GEMM on tensor cores (bf16 split) — unchanged (passing).
// ---------------------------------------------------------------------------
#define P1_SA 40
#define P1_SB 136

__global__ void __launch_bounds__(256, 2) gemm_xw_mma(const float* __restrict__ bias)
{
    __shared__ __nv_bfloat16 Ah[64 * P1_SA];
    __shared__ __nv_bfloat16 Al[64 * P1_SA];
    __shared__ __nv_bfloat16 Bh[32 * P1_SB];
    __shared__ __nv_bfloat16 Bl[32 * P1_SB];

    const int tid = threadIdx.x;
    const int bn = blockIdx.x;
    const int bm = blockIdx.y;
    const int warp = tid >> 5;
    const int lane = tid & 31;
    const int wm = (warp >> 2) * 32;
    const int wn = (warp & 3) * 32;

    const int arow = tid >> 2;
    const int acol = (tid & 3) * 8;
    const int brow = tid >> 4;
    const int bcol = (tid & 15) * 8;

    const size_t a_off = (size_t)(bm * 64 + arow) * DD + acol;
    const size_t b_off0 = (size_t)brow * G4 + bn * 128 + bcol;

    float acc[2][4][4];
#pragma unroll
    for (int mi = 0; mi < 2; mi++)
#pragma unroll
        for (int n = 0; n < 4; n++)
#pragma unroll
            for (int q = 0; q < 4; q++) acc[mi][n][q] = 0.0f;

    const int a_lrow = lane & 15;
    const int a_lcol = (lane >> 4) << 3;

    for (int k0 = 0; k0 < DD; k0 += 32) {
        *(uint4*)&Ah[arow * P1_SA + acol] = *(const uint4*)&g_xhi[a_off + k0];
        *(uint4*)&Al[arow * P1_SA + acol] = *(const uint4*)&g_xlo[a_off + k0];
#pragma unroll
        for (int i = 0; i < 2; i++) {
            size_t go = b_off0 + (size_t)(k0 + i * 16) * G4;
            *(uint4*)&Bh[(brow + i * 16) * P1_SB + bcol] = *(const uint4*)&g_whi[go];
            *(uint4*)&Bl[(brow + i * 16) * P1_SB + bcol] = *(const uint4*)&g_wlo[go];
        }
        __syncthreads();

#pragma unroll
        for (int kk = 0; kk < 32; kk += 16) {
            uint32_t ah[2][4], al[2][4], bh[2][4], bl[2][4];
#pragma unroll
            for (int mi = 0; mi < 2; mi++) {
                const __nv_bfloat16* pa =
                    &Ah[(wm + mi * 16 + a_lrow) * P1_SA + kk + a_lcol];
                ldsm_x4(ah[mi][0], ah[mi][1], ah[mi][2], ah[mi][3], pa);
                const __nv_bfloat16* pl =
                    &Al[(wm + mi * 16 + a_lrow) * P1_SA + kk + a_lcol];
                ldsm_x4(al[mi][0], al[mi][1], al[mi][2], al[mi][3], pl);
            }
#pragma unroll
            for (int g = 0; g < 2; g++) {
                const __nv_bfloat16* pb =
                    &Bh[(kk + a_lrow) * P1_SB + wn + g * 16 + a_lcol];
                ldsm_x4_t(bh[g][0], bh[g][1], bh[g][2], bh[g][3], pb);
                const __nv_bfloat16* pbl =
                    &Bl[(kk + a_lrow) * P1_SB + wn + g * 16 + a_lcol];
                ldsm_x4_t(bl[g][0], bl[g][1], bl[g][2], bl[g][3], pbl);
            }
#pragma unroll
            for (int mi = 0; mi < 2; mi++)
#pragma unroll
                for (int n = 0; n < 4; n++) {
                    uint32_t b0 = bh[n >> 1][(n & 1) * 2];
                    uint32_t b1 = bh[n >> 1][(n & 1) * 2 + 1];
                    uint32_t c0 = bl[n >> 1][(n & 1) * 2];
                    uint32_t c1 = bl[n >> 1][(n & 1) * 2 + 1];
                    mma_bf16(acc[mi][n], ah[mi], b0, b1);
                    mma_bf16(acc[mi][n], ah[mi], c0, c1);
                    mma_bf16(acc[mi][n], al[mi], b0, b1);
                }
        }
        __syncthreads();
    }

    const int r0 = bm * 64 + wm + (lane >> 2);
    const int c0 = bn * 128 + wn + (lane & 3) * 2;
#pragma unroll
    for (int mi = 0; mi < 2; mi++)
#pragma unroll
        for (int n = 0; n < 4; n++) {
            int col = c0 + n * 8;
            float bv0 = bias[col], bv1 = bias[col + 1];
            int row = r0 + mi * 16;
            float2 v0 = {acc[mi][n][0] + bv0, acc[mi][n][1] + bv1};
            float2 v1 = {acc[mi][n][2] + bv0, acc[mi][n][3] + bv1};
            *(float2*)&g_xw[(size_t)row * G4 + col] = v0;
            *(float2*)&g_xw[(size_t)(row + 8) * G4 + col] = v1;
        }
}

// ---------------------------------------------------------------------------
// Activations (fp32)
// ---------------------------------------------------------------------------
__device__ __forceinline__ float sigmoid_f(float x)
{
    float t = __expf(-fabsf(x));
    float inv = 1.0f / (1.0f + t);
    return (x >= 0.0f) ? inv : t * inv;
}

__device__ __forceinline__ float tanh_f(float x)
{
    float e = __expf(-2.0f * fabsf(x));
    float r = (1.0f - e) / (1.0f + e);
    return (x >= 0.0f) ? r : -r;
}

// ---------------------------------------------------------------------------
// Low-latency grid barrier. g_bar zeroed per launch (in-graph memset).
// arrive(): thread 0 only, AFTER __syncthreads() (orders block's stores).
// wait_release(): all threads (coalesced per-warp poll, acquire).
// ---------------------------------------------------------------------------
__device__ __forceinline__ void bar_arrive(unsigned k)
{
    unsigned old;
    asm volatile("fence.acq_rel.gpu;" ::: "memory");
    asm volatile("atom.acq_rel.gpu.global.add.u32 %0, [%1], %2;"
                 : "=r"(old) : "l"(&g_bar[0]), "r"(1u) : "memory");
    if (old == k * RBLOCKS - 1) {
        asm volatile("st.release.gpu.global.u32 [%0], %1;"
                     :: "l"(&g_bar[1]), "r"(k) : "memory");
    }
}

__device__ __forceinline__ void bar_wait(unsigned k)
{
    unsigned v;
    do {
        asm volatile("ld.acquire.gpu.global.u32 %0, [%1];"
                     : "=r"(v) : "l"(&g_bar[1]) : "memory");
    } while ((int)(v - k) < 0);
}

// ---------------------------------------------------------------------------
// Phase 2: persistent recurrence on tensor cores (structure as R4).
// ---------------------------------------------------------------------------
__global__ void __launch_bounds__(RTHREADS, 1)
lstm_rec_mma(const float* __restrict__ h0,
             const float* __restrict__ Wh,
             float* __restrict__ out)
{
    __shared__ float red[8][32][16];   // k-split partials
    __shared__ float a_s[512];         // reduced pre-activations [n][c]

    const int tid  = threadIdx.x;
    const int bid  = blockIdx.x;
    const int j0   = bid * JPB;
    const int w    = tid >> 5;
    const int lane = tid & 31;
    const int g    = lane >> 2;   // 0..7
    const int tig  = lane & 3;    // 0..3

    // ---- one-time: build Wh B-fragments in registers (hi/lo) ----
    uint2 bh[2][4], bl[2][4];
#pragma unroll
    for (int nt = 0; nt < 2; nt++) {
        int c = nt * 8 + g;
        int wcol = (c >> 2) * 512 + j0 + (c & 3);
#pragma unroll
        for (int kt = 0; kt < 4; kt++) {
            int k0 = (4 * w + kt) * 16;
            float w00 = Wh[(size_t)(k0 + 2 * tig) * G4 + wcol];
            float w01 = Wh[(size_t)(k0 + 2 * tig + 1) * G4 + wcol];
            float w10 = Wh[(size_t)(k0 + 8 + 2 * tig) * G4 + wcol];
            float w11 = Wh[(size_t)(k0 + 8 + 2 * tig + 1) * G4 + wcol];
            __nv_bfloat16 h00, h01, h10, h11, l00, l01, l10, l11;
            split1(w00, h00, l00); split1(w01, h01, l01);
            split1(w10, h10, l10); split1(w11, h11, l11);
            bh[nt][kt].x = ((uint32_t)__bfloat16_as_ushort(h01) << 16) |
                           __bfloat16_as_ushort(h00);
            bh[nt][kt].y = ((uint32_t)__bfloat16_as_ushort(h11) << 16) |
                           __bfloat16_as_ushort(h10);
            bl[nt][kt].x = ((uint32_t)__bfloat16_as_ushort(l01) << 16) |
                           __bfloat16_as_ushort(l00);
            bl[nt][kt].y = ((uint32_t)__bfloat16_as_ushort(l11) << 16) |
                           __bfloat16_as_ushort(l10);
        }
    }

    // ---- gate-thread geometry (tid < 64) ----
    const int gn   = tid >> 1;
    const int jlp  = tid & 1;
    const int f0   = j0 + 2 * jlp;
    const int w_mt   = gn >> 4;
    const int w_r    = gn & 15;
    const int w_ktg  = f0 >> 4;
    const int w_kc   = f0 & 15;
    const int w_lane = (w_r & 7) * 4 + ((w_kc & 7) >> 1);
    const int w_reg  = ((w_kc & 8) ? 2 : 0) + ((w_r & 8) ? 1 : 0);
    uint32_t* whi_p = (uint32_t*)&g_hfragHI[0][w_mt][w_ktg][w_lane] + w_reg;
    uint32_t* wlo_p = (uint32_t*)&g_hfragLO[0][w_mt][w_ktg][w_lane] + w_reg;
    const size_t fragbuf_stride = sizeof(g_hfragHI[0]) / 4;

    float c_st0 = 0.0f, c_st1 = 0.0f;

    // ---- init h0 fragments (buffer 0) ----
    if (tid < 64) {
        float v0 = h0[(size_t)gn * HH + f0];
        float v1 = h0[(size_t)gn * HH + f0 + 1];
        __nv_bfloat16 h0b, h1b, l0b, l1b;
        split1(v0, h0b, l0b); split1(v1, h1b, l1b);
        __stcg(whi_p, ((uint32_t)__bfloat16_as_ushort(h1b) << 16) |
                      __bfloat16_as_ushort(h0b));
        __stcg(wlo_p, ((uint32_t)__bfloat16_as_ushort(l1b) << 16) |
                      __bfloat16_as_ushort(l0b));
    }
    __syncthreads();
    if (tid == 0) bar_arrive(1);
    bar_wait(1);

    // ---- xw prefetch mapping ----
    const int o0 = 2 * tid;
    const int xn = o0 >> 4;
    const int xc0 = o0 & 15;
    const int xc1 = xc0 + 1;
    const size_t xw_base0 = (size_t)xn * TT * G4 + (xc0 >> 2) * 512 + j0 + (xc0 & 3);
    const size_t xw_base1 = (size_t)xn * TT * G4 + (xc1 >> 2) * 512 + j0 + (xc1 & 3);

    float xw0 = __ldcg(&g_xw[xw_base0]);
    float xw1 = __ldcg(&g_xw[xw_base1]);

    for (int t = 0; t < TT; t++) {
        // prefetch next step's xw
        int tn = (t + 1 < TT) ? t + 1 : t;
        float nxw0 = __ldcg(&g_xw[xw_base0 + (size_t)tn * G4]);
        float nxw1 = __ldcg(&g_xw[xw_base1 + (size_t)tn * G4]);

        // load h_t A-fragments
        const int p = t & 1;
        uint4 ahi[2][4], alo[2][4];
#pragma unroll
        for (int mt = 0; mt < 2; mt++)
#pragma unroll
            for (int kt = 0; kt < 4; kt++) {
                ahi[mt][kt] = __ldcg(&g_hfragHI[p][mt][4 * w + kt][lane]);
                alo[mt][kt] = __ldcg(&g_hfragLO[p][mt][4 * w + kt][lane]);
            }

        // split-term MMA with two accumulator sets (shorter dep chain)
        float acc[2][2][4], acl[2][2][4];
#pragma unroll
        for (int mt = 0; mt < 2; mt++)
#pragma unroll
            for (int nt = 0; nt < 2; nt++)
#pragma unroll
                for (int q = 0; q < 4; q++) { acc[mt][nt][q] = 0.0f; acl[mt][nt][q] = 0.0f; }

#pragma unroll
        for (int kt = 0; kt < 4; kt++)
#pragma unroll
            for (int mt = 0; mt < 2; mt++)
#pragma unroll
                for (int nt = 0; nt < 2; nt++) {
                    mma_bf16(acc[mt][nt], (const uint32_t*)&ahi[mt][kt],
                             bh[nt][kt].x, bh[nt][kt].y);
                    mma_bf16(acc[mt][nt], (const uint32_t*)&ahi[mt][kt],
                             bl[nt][kt].x, bl[nt][kt].y);
                    mma_bf16(acl[mt][nt], (const uint32_t*)&alo[mt][kt],
                             bh[nt][kt].x, bh[nt][kt].y);
                }

        // store k-split partials (merge the two accumulator sets here)
#pragma unroll
        for (int mt = 0; mt < 2; mt++)
#pragma unroll
            for (int nt = 0; nt < 2; nt++) {
                *(float2*)&red[w][mt * 16 + g][nt * 8 + tig * 2] =
                    make_float2(acc[mt][nt][0] + acl[mt][nt][0],
                                acc[mt][nt][1] + acl[mt][nt][1]);
                *(float2*)&red[w][mt * 16 + g + 8][nt * 8 + tig * 2] =
                    make_float2(acc[mt][nt][2] + acl[mt][nt][2],
                                acc[mt][nt][3] + acl[mt][nt][3]);
            }
        __syncthreads();

        // reduce 8 warps + xw -> a_s
        {
            float s0 = xw0, s1 = xw1;
#pragma unroll
            for (int ww = 0; ww < 8; ww++) {
                float2 r = *(const float2*)&red[ww][xn][xc0];
                s0 += r.x; s1 += r.y;
            }
            *(float2*)&a_s[o0] = make_float2(s0, s1);
        }
        __syncthreads();

        // gates
        if (tid < 64) {
            const float* ap = &a_s[gn * CPB + 2 * jlp];
            float2 ai = *(const float2*)(ap + 0);
            float2 af = *(const float2*)(ap + 4);
            float2 ao = *(const float2*)(ap + 8);
            float2 ag = *(const float2*)(ap + 12);

            float i0 = sigmoid_f(ai.x), i1 = sigmoid_f(ai.y);
            float fg0 = sigmoid_f(af.x), fg1 = sigmoid_f(af.y);
            float oo0 = sigmoid_f(ao.x), oo1 = sigmoid_f(ao.y);
            float gg0 = tanh_f(ag.x),   gg1 = tanh_f(ag.y);

            c_st0 = fmaf(fg0, c_st0, i0 * gg0);
            c_st1 = fmaf(fg1, c_st1, i1 * gg1);
            float hn0 = oo0 * tanh_f(c_st0);
            float hn1 = oo1 * tanh_f(c_st1);

            *(float2*)&out[((size_t)gn * TT + t) * HH + f0] = make_float2(hn0, hn1);

            __nv_bfloat16 hb0, hb1, lb0, lb1;
            split1(hn0, hb0, lb0); split1(hn1, hb1, lb1);
            size_t boff = (size_t)((t + 1) & 1) * fragbuf_stride;
            __stcg(whi_p + boff, ((uint32_t)__bfloat16_as_ushort(hb1) << 16) |
                                 __bfloat16_as_ushort(hb0));
            __stcg(wlo_p + boff, ((uint32_t)__bfloat16_as_ushort(lb1) << 16) |
                                 __bfloat16_as_ushort(lb0));
        }
        xw0 = nxw0; xw1 = nxw1;

        __syncthreads();
        if (tid == 0) bar_arrive(t + 2);
        bar_wait(t + 2);
    }
}

// ---------------------------------------------------------------------------
// kernel_launch
// ---------------------------------------------------------------------------
extern "C" void kernel_launch(void* const* d_in, const int* in_sizes, int n_in,
                              void* d_out, int out_size)
{
    const float* x  = (const float*)d_in[0];  // (32, 1024, 512)
    const float* h0 = (const float*)d_in[1];  // (32, 512)
    const float* Wx = (const float*)d_in[2];  // (512, 2048)
    const float* Wh = (const float*)d_in[3];  // (512, 2048)
    const float* b  = (const float*)d_in[4];  // (2048,)
    float* out = (float*)d_out;               // (32, 1024, 512)

    (void)in_sizes; (void)n_in; (void)out_size;

    // zero the barrier words (in-graph memset node; runs before kernels, stream order)
    void* bar_ptr = nullptr;
    cudaGetSymbolAddress(&bar_ptr, g_bar);
    cudaMemsetAsync(bar_ptr, 0, 2 * sizeof(unsigned));

    // Phase 1: split + tensor-core GEMM
    size_t nx4 = (size_t)MROWS * DD / 4;
    size_t nw4 = (size_t)DD * G4 / 4;
    split_kernel_x<<<(unsigned)((nx4 + 255) / 256), 256>>>(x);
    split_kernel_w<<<(unsigned)((nw4 + 255) / 256), 256>>>(Wx);

    dim3 g1(G4 / 128, MROWS / 64);
    gemm_xw_mma<<<g1, 256>>>(b);

    // Phase 2: persistent tensor-core recurrence
    lstm_rec_mma<<<RBLOCKS, RTHREADS>>>(h0, Wh, out);
}

// round 6
// speedup vs baseline: 1.1821x; 1.1821x over previous
#include <cuda_runtime.h>
#include <cuda_bf16.h>
#include <math.h>
#include <stdint.h>

// Problem constants
#define NB 32            // batch
#define TT 1024          // timesteps
#define DD 512           // input dim
#define HH 512           // hidden dim
#define G4 2048          // 4*H
#define MROWS (NB * TT)  // 32768

// Recurrent kernel config
#define RBLOCKS 64       // persistent blocks
#define RTHREADS 256
#define JPB 8            // h-columns per block (64*8 = 512)
#define CPB 32           // gate columns per block

// Scratch (device globals; no cudaMalloc allowed)
__device__ float g_xw[(size_t)MROWS * G4];   // 268 MB: x @ Wx + b
__device__ unsigned g_bar[2];                // [0]=count, [1]=sense; zeroed per launch

// h exchanged in MMA A-fragment layout: [buf][mt][ktile][lane] -> uint4
__device__ uint4 g_hfragHI[2][2][32][32];
__device__ uint4 g_hfragLO[2][2][32][32];

// bf16 hi/lo split buffers for tensor-core phase 1
__device__ __nv_bfloat16 g_xhi[(size_t)MROWS * DD];
__device__ __nv_bfloat16 g_xlo[(size_t)MROWS * DD];
__device__ __nv_bfloat16 g_whi[(size_t)DD * G4];
__device__ __nv_bfloat16 g_wlo[(size_t)DD * G4];

// ---------------------------------------------------------------------------
// fp32 -> bf16 hi + lo split
// ---------------------------------------------------------------------------
__device__ __forceinline__ void split1(float v, __nv_bfloat16& h, __nv_bfloat16& l)
{
    h = __float2bfloat16(v);
    l = __float2bfloat16(v - __bfloat162float(h));
}

__global__ void __launch_bounds__(256) split_kernel_x(const float* __restrict__ src)
{
    size_t i = (size_t)blockIdx.x * blockDim.x + threadIdx.x;
    size_t n4 = (size_t)MROWS * DD / 4;
    if (i >= n4) return;
    float4 v = ((const float4*)src)[i];
    __nv_bfloat16 h0, h1, h2, h3, l0, l1, l2, l3;
    split1(v.x, h0, l0); split1(v.y, h1, l1);
    split1(v.z, h2, l2); split1(v.w, h3, l3);
    ((__nv_bfloat162*)g_xhi)[2 * i]     = __nv_bfloat162(h0, h1);
    ((__nv_bfloat162*)g_xhi)[2 * i + 1] = __nv_bfloat162(h2, h3);
    ((__nv_bfloat162*)g_xlo)[2 * i]     = __nv_bfloat162(l0, l1);
    ((__nv_bfloat162*)g_xlo)[2 * i + 1] = __nv_bfloat162(l2, l3);
}

__global__ void __launch_bounds__(256) split_kernel_w(const float* __restrict__ src)
{
    size_t i = (size_t)blockIdx.x * blockDim.x + threadIdx.x;
    size_t n4 = (size_t)DD * G4 / 4;
    if (i >= n4) return;
    float4 v = ((const float4*)src)[i];
    __nv_bfloat16 h0, h1, h2, h3, l0, l1, l2, l3;
    split1(v.x, h0, l0); split1(v.y, h1, l1);
    split1(v.z, h2, l2); split1(v.w, h3, l3);
    ((__nv_bfloat162*)g_whi)[2 * i]     = __nv_bfloat162(h0, h1);
    ((__nv_bfloat162*)g_whi)[2 * i + 1] = __nv_bfloat162(h2, h3);
    ((__nv_bfloat162*)g_wlo)[2 * i]     = __nv_bfloat162(l0, l1);
    ((__nv_bfloat162*)g_wlo)[2 * i + 1] = __nv_bfloat162(l2, l3);
}

// ---------------------------------------------------------------------------
// PTX wrappers
// ---------------------------------------------------------------------------
__device__ __forceinline__ void ldsm_x4(uint32_t& r0, uint32_t& r1, uint32_t& r2,
                                        uint32_t& r3, const void* p)
{
    uint32_t a = (uint32_t)__cvta_generic_to_shared(p);
    asm volatile("ldmatrix.sync.aligned.m8n8.x4.shared.b16 {%0,%1,%2,%3}, [%4];"
                 : "=r"(r0), "=r"(r1), "=r"(r2), "=r"(r3) : "r"(a));
}

__device__ __forceinline__ void ldsm_x4_t(uint32_t& r0, uint32_t& r1, uint32_t& r2,
                                          uint32_t& r3, const void* p)
{
    uint32_t a = (uint32_t)__cvta_generic_to_shared(p);
    asm volatile("ldmatrix.sync.aligned.m8n8.x4.trans.shared.b16 {%0,%1,%2,%3}, [%4];"
                 : "=r"(r0), "=r"(r1), "=r"(r2), "=r"(r3) : "r"(a));
}

__device__ __forceinline__ void mma_bf16(float* c, const uint32_t* a,
                                         uint32_t b0, uint32_t b1)
{
    asm volatile(
        "mma.sync.aligned.m16n8k16.row.col.f32.bf16.bf16.f32 "
        "{%0,%1,%2,%3},{%4,%5,%6,%7},{%8,%9},{%0,%1,%2,%3};"
        : "+f"(c[0]), "+f"(c[1]), "+f"(c[2]), "+f"(c[3])
        : "r"(a[0]), "r"(a[1]), "r"(a[2]), "r"(a[3]), "r"(b0), "r"(b1));
}

// ---------------------------------------------------------------------------
// Phase 1 GEMM on tensor cores (bf16 split) — unchanged (passing).
// ---------------------------------------------------------------------------
#define P1_SA 40
#define P1_SB 136

__global__ void __launch_bounds__(256, 2) gemm_xw_mma(const float* __restrict__ bias)
{
    __shared__ __nv_bfloat16 Ah[64 * P1_SA];
    __shared__ __nv_bfloat16 Al[64 * P1_SA];
    __shared__ __nv_bfloat16 Bh[32 * P1_SB];
    __shared__ __nv_bfloat16 Bl[32 * P1_SB];

    const int tid = threadIdx.x;
    const int bn = blockIdx.x;
    const int bm = blockIdx.y;
    const int warp = tid >> 5;
    const int lane = tid & 31;
    const int wm = (warp >> 2) * 32;
    const int wn = (warp & 3) * 32;

    const int arow = tid >> 2;
    const int acol = (tid & 3) * 8;
    const int brow = tid >> 4;
    const int bcol = (tid & 15) * 8;

    const size_t a_off = (size_t)(bm * 64 + arow) * DD + acol;
    const size_t b_off0 = (size_t)brow * G4 + bn * 128 + bcol;

    float acc[2][4][4];
#pragma unroll
    for (int mi = 0; mi < 2; mi++)
#pragma unroll
        for (int n = 0; n < 4; n++)
#pragma unroll
            for (int q = 0; q < 4; q++) acc[mi][n][q] = 0.0f;

    const int a_lrow = lane & 15;
    const int a_lcol = (lane >> 4) << 3;

    for (int k0 = 0; k0 < DD; k0 += 32) {
        *(uint4*)&Ah[arow * P1_SA + acol] = *(const uint4*)&g_xhi[a_off + k0];
        *(uint4*)&Al[arow * P1_SA + acol] = *(const uint4*)&g_xlo[a_off + k0];
#pragma unroll
        for (int i = 0; i < 2; i++) {
            size_t go = b_off0 + (size_t)(k0 + i * 16) * G4;
            *(uint4*)&Bh[(brow + i * 16) * P1_SB + bcol] = *(const uint4*)&g_whi[go];
            *(uint4*)&Bl[(brow + i * 16) * P1_SB + bcol] = *(const uint4*)&g_wlo[go];
        }
        __syncthreads();

#pragma unroll
        for (int kk = 0; kk < 32; kk += 16) {
            uint32_t ah[2][4], al[2][4], bh[2][4], bl[2][4];
#pragma unroll
            for (int mi = 0; mi < 2; mi++) {
                const __nv_bfloat16* pa =
                    &Ah[(wm + mi * 16 + a_lrow) * P1_SA + kk + a_lcol];
                ldsm_x4(ah[mi][0], ah[mi][1], ah[mi][2], ah[mi][3], pa);
                const __nv_bfloat16* pl =
                    &Al[(wm + mi * 16 + a_lrow) * P1_SA + kk + a_lcol];
                ldsm_x4(al[mi][0], al[mi][1], al[mi][2], al[mi][3], pl);
            }
#pragma unroll
            for (int g = 0; g < 2; g++) {
                const __nv_bfloat16* pb =
                    &Bh[(kk + a_lrow) * P1_SB + wn + g * 16 + a_lcol];
                ldsm_x4_t(bh[g][0], bh[g][1], bh[g][2], bh[g][3], pb);
                const __nv_bfloat16* pbl =
                    &Bl[(kk + a_lrow) * P1_SB + wn + g * 16 + a_lcol];
                ldsm_x4_t(bl[g][0], bl[g][1], bl[g][2], bl[g][3], pbl);
            }
#pragma unroll
            for (int mi = 0; mi < 2; mi++)
#pragma unroll
                for (int n = 0; n < 4; n++) {
                    uint32_t b0 = bh[n >> 1][(n & 1) * 2];
                    uint32_t b1 = bh[n >> 1][(n & 1) * 2 + 1];
                    uint32_t c0 = bl[n >> 1][(n & 1) * 2];
                    uint32_t c1 = bl[n >> 1][(n & 1) * 2 + 1];
                    mma_bf16(acc[mi][n], ah[mi], b0, b1);
                    mma_bf16(acc[mi][n], ah[mi], c0, c1);
                    mma_bf16(acc[mi][n], al[mi], b0, b1);
                }
        }
        __syncthreads();
    }

    const int r0 = bm * 64 + wm + (lane >> 2);
    const int c0 = bn * 128 + wn + (lane & 3) * 2;
#pragma unroll
    for (int mi = 0; mi < 2; mi++)
#pragma unroll
        for (int n = 0; n < 4; n++) {
            int col = c0 + n * 8;
            float bv0 = bias[col], bv1 = bias[col + 1];
            int row = r0 + mi * 16;
            float2 v0 = {acc[mi][n][0] + bv0, acc[mi][n][1] + bv1};
            float2 v1 = {acc[mi][n][2] + bv0, acc[mi][n][3] + bv1};
            *(float2*)&g_xw[(size_t)row * G4 + col] = v0;
            *(float2*)&g_xw[(size_t)(row + 8) * G4 + col] = v1;
        }
}

// ---------------------------------------------------------------------------
// Activations (fp32)
// ---------------------------------------------------------------------------
__device__ __forceinline__ float sigmoid_f(float x)
{
    float t = __expf(-fabsf(x));
    float inv = 1.0f / (1.0f + t);
    return (x >= 0.0f) ? inv : t * inv;
}

__device__ __forceinline__ float tanh_f(float x)
{
    float e = __expf(-2.0f * fabsf(x));
    float r = (1.0f - e) / (1.0f + e);
    return (x >= 0.0f) ? r : -r;
}

// ---------------------------------------------------------------------------
// Grid barrier: thread 0 only arrives AND polls (minimal L2 contention),
// __syncthreads() fans out. Monotonic count (memset per launch), thread-0
// gpu-scope fence replaces the all-thread __threadfence.
// ---------------------------------------------------------------------------
__device__ __forceinline__ void bar_epoch(unsigned k)
{
    __syncthreads();
    if (threadIdx.x == 0) {
        unsigned old;
        asm volatile("fence.acq_rel.gpu;" ::: "memory");
        asm volatile("atom.relaxed.gpu.global.add.u32 %0, [%1], %2;"
                     : "=r"(old) : "l"(&g_bar[0]), "r"(1u) : "memory");
        if (old == k * RBLOCKS - 1) {
            asm volatile("st.release.gpu.global.u32 [%0], %1;"
                         :: "l"(&g_bar[1]), "r"(k) : "memory");
        } else {
            unsigned v;
            do {
                asm volatile("ld.acquire.gpu.global.u32 %0, [%1];"
                             : "=r"(v) : "l"(&g_bar[1]) : "memory");
            } while ((int)(v - k) < 0);
        }
    }
    __syncthreads();
}

// ---------------------------------------------------------------------------
// Phase 2: persistent recurrence on tensor cores.
// 64 blocks x 256 threads (8 warps). Block b owns 8 h-cols (j0=8b) = 32 gate
// cols packed c = gate*8 + jl. Warp w = K-chunk [64w,64w+64); covers all 4
// n8-tiles (96 HMMA/warp/step). Wh B-fragments in registers (hi/lo).
// ---------------------------------------------------------------------------
#define REDS 36   // padded row stride for red (floats)

__global__ void __launch_bounds__(RTHREADS, 1)
lstm_rec_mma(const float* __restrict__ h0,
             const float* __restrict__ Wh,
             float* __restrict__ out)
{
    __shared__ float red[8][32][REDS];   // k-split partials (padded)
    __shared__ float a_s[1024];          // reduced pre-activations [n][c]

    const int tid  = threadIdx.x;
    const int bid  = blockIdx.x;
    const int j0   = bid * JPB;
    const int w    = tid >> 5;    // kg 0..7
    const int lane = tid & 31;
    const int g    = lane >> 2;   // 0..7
    const int tig  = lane & 3;    // 0..3

    // ---- one-time: Wh B-fragments in registers (hi/lo), 4 n-tiles ----
    uint2 bh[4][4], bl[4][4];
#pragma unroll
    for (int nt = 0; nt < 4; nt++) {
        int c = nt * 8 + g;                       // packed col 0..31
        int wcol = (c >> 3) * 512 + j0 + (c & 7); // global Wh column
#pragma unroll
        for (int kt = 0; kt < 4; kt++) {
            int k0 = (4 * w + kt) * 16;
            float w00 = Wh[(size_t)(k0 + 2 * tig) * G4 + wcol];
            float w01 = Wh[(size_t)(k0 + 2 * tig + 1) * G4 + wcol];
            float w10 = Wh[(size_t)(k0 + 8 + 2 * tig) * G4 + wcol];
            float w11 = Wh[(size_t)(k0 + 8 + 2 * tig + 1) * G4 + wcol];
            __nv_bfloat16 h00, h01, h10, h11, l00, l01, l10, l11;
            split1(w00, h00, l00); split1(w01, h01, l01);
            split1(w10, h10, l10); split1(w11, h11, l11);
            bh[nt][kt].x = ((uint32_t)__bfloat16_as_ushort(h01) << 16) |
                           __bfloat16_as_ushort(h00);
            bh[nt][kt].y = ((uint32_t)__bfloat16_as_ushort(h11) << 16) |
                           __bfloat16_as_ushort(h10);
            bl[nt][kt].x = ((uint32_t)__bfloat16_as_ushort(l01) << 16) |
                           __bfloat16_as_ushort(l00);
            bl[nt][kt].y = ((uint32_t)__bfloat16_as_ushort(l11) << 16) |
                           __bfloat16_as_ushort(l10);
        }
    }

    // ---- gate-thread geometry (tid < 128): owns (gn, f0, f0+1) ----
    const int gn   = tid >> 2;       // batch row 0..31
    const int jlp  = tid & 3;        // 0..3
    const int f0   = j0 + 2 * jlp;   // even global h column
    const int w_mt   = gn >> 4;
    const int w_r    = gn & 15;
    const int w_ktg  = f0 >> 4;
    const int w_kc   = f0 & 15;
    const int w_lane = (w_r & 7) * 4 + ((w_kc & 7) >> 1);
    const int w_reg  = ((w_kc & 8) ? 2 : 0) + ((w_r & 8) ? 1 : 0);
    uint32_t* whi_p = (uint32_t*)&g_hfragHI[0][w_mt][w_ktg][w_lane] + w_reg;
    uint32_t* wlo_p = (uint32_t*)&g_hfragLO[0][w_mt][w_ktg][w_lane] + w_reg;
    const size_t fragbuf_stride = sizeof(g_hfragHI[0]) / 4;

    float c_st0 = 0.0f, c_st1 = 0.0f;

    // ---- init h0 fragments (buffer 0) ----
    if (tid < 128) {
        float v0 = h0[(size_t)gn * HH + f0];
        float v1 = h0[(size_t)gn * HH + f0 + 1];
        __nv_bfloat16 h0b, h1b, l0b, l1b;
        split1(v0, h0b, l0b); split1(v1, h1b, l1b);
        __stcg(whi_p, ((uint32_t)__bfloat16_as_ushort(h1b) << 16) |
                      __bfloat16_as_ushort(h0b));
        __stcg(wlo_p, ((uint32_t)__bfloat16_as_ushort(l1b) << 16) |
                      __bfloat16_as_ushort(l0b));
    }
    bar_epoch(1);

    // ---- xw mapping: thread reduces 4 outputs o = 4*tid .. 4*tid+3 ----
    const int o0  = 4 * tid;
    const int xn  = o0 >> 5;        // batch row
    const int xc0 = o0 & 31;        // packed col (4-aligned, same gate group)
    const size_t xw_base =
        (size_t)xn * TT * G4 + (xc0 >> 3) * 512 + j0 + (xc0 & 7);

    float4 xw = *(const float4*)&g_xw[xw_base];

    for (int t = 0; t < TT; t++) {
        // prefetch next step's xw
        int tn = (t + 1 < TT) ? t + 1 : t;
        float4 nxw = __ldcg((const float4*)&g_xw[xw_base + (size_t)tn * G4]);

        // load h_t A-fragments
        const int p = t & 1;
        uint4 ahi[2][4], alo[2][4];
#pragma unroll
        for (int mt = 0; mt < 2; mt++)
#pragma unroll
            for (int kt = 0; kt < 4; kt++) {
                ahi[mt][kt] = __ldcg(&g_hfragHI[p][mt][4 * w + kt][lane]);
                alo[mt][kt] = __ldcg(&g_hfragLO[p][mt][4 * w + kt][lane]);
            }

        // split-term MMA, two accumulator sets (shorter dep chains)
        float acc[2][4][4], acl[2][4][4];
#pragma unroll
        for (int mt = 0; mt < 2; mt++)
#pragma unroll
            for (int nt = 0; nt < 4; nt++)
#pragma unroll
                for (int q = 0; q < 4; q++) { acc[mt][nt][q] = 0.0f; acl[mt][nt][q] = 0.0f; }

#pragma unroll
        for (int kt = 0; kt < 4; kt++)
#pragma unroll
            for (int mt = 0; mt < 2; mt++)
#pragma unroll
                for (int nt = 0; nt < 4; nt++) {
                    mma_bf16(acc[mt][nt], (const uint32_t*)&ahi[mt][kt],
                             bh[nt][kt].x, bh[nt][kt].y);
                    mma_bf16(acc[mt][nt], (const uint32_t*)&ahi[mt][kt],
                             bl[nt][kt].x, bl[nt][kt].y);
                    mma_bf16(acl[mt][nt], (const uint32_t*)&alo[mt][kt],
                             bh[nt][kt].x, bh[nt][kt].y);
                }

        // store k-split partials (merge lo-term here)
#pragma unroll
        for (int mt = 0; mt < 2; mt++)
#pragma unroll
            for (int nt = 0; nt < 4; nt++) {
                *(float2*)&red[w][mt * 16 + g][nt * 8 + tig * 2] =
                    make_float2(acc[mt][nt][0] + acl[mt][nt][0],
                                acc[mt][nt][1] + acl[mt][nt][1]);
                *(float2*)&red[w][mt * 16 + g + 8][nt * 8 + tig * 2] =
                    make_float2(acc[mt][nt][2] + acl[mt][nt][2],
                                acc[mt][nt][3] + acl[mt][nt][3]);
            }
        __syncthreads();

        // reduce 8 k-chunks + xw -> a_s (4 outputs per thread)
        {
            float s0 = xw.x, s1 = xw.y, s2 = xw.z, s3 = xw.w;
#pragma unroll
            for (int kg = 0; kg < 8; kg++) {
                float4 r = *(const float4*)&red[kg][xn][xc0];
                s0 += r.x; s1 += r.y; s2 += r.z; s3 += r.w;
            }
            *(float4*)&a_s[o0] = make_float4(s0, s1, s2, s3);
        }
        __syncthreads();

        // gates: tid<128 handles (gn, f0) and (gn, f0+1)
        if (tid < 128) {
            const float* ap = &a_s[gn * CPB + 2 * jlp];
            float2 ai = *(const float2*)(ap + 0);
            float2 af = *(const float2*)(ap + 8);
            float2 ao = *(const float2*)(ap + 16);
            float2 ag = *(const float2*)(ap + 24);

            float i0 = sigmoid_f(ai.x), i1 = sigmoid_f(ai.y);
            float fg0 = sigmoid_f(af.x), fg1 = sigmoid_f(af.y);
            float oo0 = sigmoid_f(ao.x), oo1 = sigmoid_f(ao.y);
            float gg0 = tanh_f(ag.x),   gg1 = tanh_f(ag.y);

            c_st0 = fmaf(fg0, c_st0, i0 * gg0);
            c_st1 = fmaf(fg1, c_st1, i1 * gg1);
            float hn0 = oo0 * tanh_f(c_st0);
            float hn1 = oo1 * tanh_f(c_st1);

            *(float2*)&out[((size_t)gn * TT + t) * HH + f0] = make_float2(hn0, hn1);

            __nv_bfloat16 hb0, hb1, lb0, lb1;
            split1(hn0, hb0, lb0); split1(hn1, hb1, lb1);
            size_t boff = (size_t)((t + 1) & 1) * fragbuf_stride;
            __stcg(whi_p + boff, ((uint32_t)__bfloat16_as_ushort(hb1) << 16) |
                                 __bfloat16_as_ushort(hb0));
            __stcg(wlo_p + boff, ((uint32_t)__bfloat16_as_ushort(lb1) << 16) |
                                 __bfloat16_as_ushort(lb0));
        }
        xw = nxw;

        bar_epoch(t + 2);
    }
}

// ---------------------------------------------------------------------------
// kernel_launch
// ---------------------------------------------------------------------------
extern "C" void kernel_launch(void* const* d_in, const int* in_sizes, int n_in,
                              void* d_out, int out_size)
{
    const float* x  = (const float*)d_in[0];  // (32, 1024, 512)
    const float* h0 = (const float*)d_in[1];  // (32, 512)
    const float* Wx = (const float*)d_in[2];  // (512, 2048)
    const float* Wh = (const float*)d_in[3];  // (512, 2048)
    const float* b  = (const float*)d_in[4];  // (2048,)
    float* out = (float*)d_out;               // (32, 1024, 512)

    (void)in_sizes; (void)n_in; (void)out_size;

    // zero barrier words (in-graph memset node, stream-ordered before kernels)
    void* bar_ptr = nullptr;
    cudaGetSymbolAddress(&bar_ptr, g_bar);
    cudaMemsetAsync(bar_ptr, 0, 2 * sizeof(unsigned));

    // Phase 1: split + tensor-core GEMM
    size_t nx4 = (size_t)MROWS * DD / 4;
    size_t nw4 = (size_t)DD * G4 / 4;
    split_kernel_x<<<(unsigned)((nx4 + 255) / 256), 256>>>(x);
    split_kernel_w<<<(unsigned)((nw4 + 255) / 256), 256>>>(Wx);

    dim3 g1(G4 / 128, MROWS / 64);
    gemm_xw_mma<<<g1, 256>>>(b);

    // Phase 2: persistent tensor-core recurrence
    lstm_rec_mma<<<RBLOCKS, RTHREADS>>>(h0, Wh, out);
}